// round 3
// baseline (speedup 1.0000x reference)
#include <cuda_runtime.h>
#include <cstddef>

// Problem shape (fixed by dataset): target [B=32, T=4, N=512] f32
// Output: source [B, 2, N, N] f32, optionally followed by target copy.
#define BN   512
#define BT   4
#define BB   32
#define NMASK 511
#define KTILE 8

// Scratch (no allocations allowed): spectra + twiddle table
__device__ float2 g_y[BB * BT * BN];   // 512 KB
__device__ float2 g_tw[BN];            // tw[j] = exp(-2*pi*i*j/512)

// ---------------------------------------------------------------------------
// Twiddle table in double precision (accuracy for the triple products)
// ---------------------------------------------------------------------------
__global__ void twiddle_kernel() {
    int j = threadIdx.x;
    double ang = -2.0 * 3.141592653589793238462643383279502884 * (double)j / (double)BN;
    g_tw[j] = make_float2((float)cos(ang), (float)sin(ang));
}

// ---------------------------------------------------------------------------
// Two-stage DFT, N = 512 = 8 x 64.
//   n = 64a + b   (a in [0,8), b in [0,64))
//   Z[b][r] = sum_a x[64a+b] * W512^{64 r a}         (r = k mod 8)
//   y[k]    = sum_b W512^{k b} * Z[b][k mod 8]
// One block per (batch,t) row, 512 threads.
// ---------------------------------------------------------------------------
__global__ void dft_kernel(const float* __restrict__ x) {
    __shared__ float  sx[BN];
    __shared__ float2 stw[BN];
    __shared__ float2 sz[BN];      // Z stored as sz[b*8 + r]

    const int row = blockIdx.x;    // 0..127 = b*BT + t
    const int tid = threadIdx.x;

    sx[tid]  = x[(size_t)row * BN + tid];
    stw[tid] = g_tw[tid];
    __syncthreads();

    // Stage B: each thread computes one Z[b][r]
    {
        const int b = tid >> 3;
        const int r = tid & 7;
        float zr = 0.f, zi = 0.f;
#pragma unroll
        for (int a = 0; a < 8; a++) {
            float  xv = sx[64 * a + b];
            float2 w  = stw[(64 * r * a) & NMASK];
            zr = fmaf(xv, w.x, zr);
            zi = fmaf(xv, w.y, zi);
        }
        sz[tid] = make_float2(zr, zi);
    }
    __syncthreads();

    // Stage C: thread k sums 64 terms
    {
        const int k = tid;
        const int r = k & 7;
        float ar = 0.f, ai = 0.f;
        int idx = 0;  // (k*b) mod 512, incremental
#pragma unroll 8
        for (int b = 0; b < 64; b++) {
            float2 w = stw[idx];
            float2 z = sz[b * 8 + r];
            ar = fmaf(w.x, z.x, fmaf(-w.y, z.y, ar));
            ai = fmaf(w.x, z.y, fmaf( w.y, z.x, ai));
            idx = (idx + k) & NMASK;
        }
        g_y[(size_t)row * BN + k] = make_float2(ar, ai);
    }
}

// ---------------------------------------------------------------------------
// Bispectrum: Bx[k,l] = y[k] * conj(y[l]) * y[(l-k) mod N], mean over t.
// Grid: (N/KTILE, B). Block: 512 threads (one per l).
// Each block loads the 4 t-spectra for its batch ONCE into shared (16 KB)
// and produces KTILE=8 k-rows -> amortizes L2 reads of g_y 8x.
// ---------------------------------------------------------------------------
__global__ void bispec_kernel(float* __restrict__ out) {
    __shared__ float2 sy[BT][BN];

    const int b  = blockIdx.y;
    const int k0 = blockIdx.x * KTILE;
    const int l  = threadIdx.x;

#pragma unroll
    for (int t = 0; t < BT; t++)
        sy[t][l] = g_y[((size_t)b * BT + t) * BN + l];
    __syncthreads();

    float2 yl[BT];
#pragma unroll
    for (int t = 0; t < BT; t++) yl[t] = sy[t][l];

    float* outb = out + (size_t)b * 2 * BN * BN;

#pragma unroll
    for (int kk = 0; kk < KTILE; kk++) {
        const int k = k0 + kk;
        const int m = (l - k) & NMASK;   // power-of-2 mod handles negatives
        float ar = 0.f, ai = 0.f;
#pragma unroll
        for (int t = 0; t < BT; t++) {
            float2 yk = sy[t][k];        // warp-broadcast
            float2 ym = sy[t][m];        // consecutive per lane -> conflict-free
            // p = y[k] * conj(y[l])
            float pr = fmaf(yk.x, yl[t].x,  yk.y * yl[t].y);
            float pi = fmaf(yk.y, yl[t].x, -yk.x * yl[t].y);
            // Bx = p * y[m]
            ar = fmaf(pr, ym.x, fmaf(-pi, ym.y, ar));
            ai = fmaf(pr, ym.y, fmaf( pi, ym.x, ai));
        }
        outb[(size_t)k * BN + l]            = ar * 0.25f;   // real channel
        outb[(size_t)BN * BN + (size_t)k * BN + l] = ai * 0.25f;   // imag channel
    }
}

// Pass-through copy of target (only if the harness output includes it)
__global__ void copy_kernel(float* __restrict__ dst, const float* __restrict__ src, int n) {
    int i = blockIdx.x * blockDim.x + threadIdx.x;
    if (i < n) dst[i] = src[i];
}

extern "C" void kernel_launch(void* const* d_in, const int* in_sizes, int n_in,
                              void* d_out, int out_size) {
    const float* x   = (const float*)d_in[0];
    float*       out = (float*)d_out;

    twiddle_kernel<<<1, BN>>>();
    dft_kernel<<<BB * BT, BN>>>(x);
    bispec_kernel<<<dim3(BN / KTILE, BB), BN>>>(out);

    const int src_elems = BB * 2 * BN * BN;   // 16,777,216
    if (out_size > src_elems) {
        int tail = out_size - src_elems;      // expected 32*4*512 = 65,536
        if (tail > in_sizes[0]) tail = in_sizes[0];
        copy_kernel<<<(tail + 255) / 256, 256>>>(out + src_elems, x, tail);
    }
}

// round 4
// speedup vs baseline: 1.1375x; 1.1375x over previous
#include <cuda_runtime.h>
#include <cstddef>

// Shape fixed by dataset: target [B=32, T=4, N=512] f32
// Output: source [B, 2, N, N] f32  (+ optional target pass-through tail)
#define BN    512
#define BT    4
#define BB    32
#define NMASK 511
#define KTILE 8
#define SRC_ELEMS (BB * 2 * BN * BN)   // 16,777,216

// Scratch: per-(b,t) spectra (no allocations allowed)
__device__ float2 g_y[BB * BT * BN];   // 512 KB

// ---------------------------------------------------------------------------
// Two-stage DFT (N = 512 = 8 x 64), twiddles computed in-block via sincospif,
// tail pass-through copy fused in (128 blocks x 512 threads == tail size).
//   n = 64a + b ;  Z[b][r] = sum_a x[64a+b] W^{64 r a} ;  y[k] = sum_b W^{kb} Z[b][k&7]
// ---------------------------------------------------------------------------
__global__ void dft_kernel(const float* __restrict__ x,
                           float* __restrict__ out, int out_size) {
    __shared__ float  sx[BN];
    __shared__ float2 stw[BN];
    __shared__ float2 sz[BN];          // Z as sz[b*8 + r]

    const int row = blockIdx.x;        // 0..127 = b*BT + t
    const int tid = threadIdx.x;

    sx[tid] = x[(size_t)row * BN + tid];
    {
        // tw[j] = exp(-2*pi*i*j/512): angle = pi * (-j/256)
        float s, c;
        sincospif(-(float)tid * (1.0f / 256.0f), &s, &c);
        stw[tid] = make_float2(c, s);
    }
    __syncthreads();

    // Stage B: one Z[b][r] per thread
    {
        const int b = tid >> 3;
        const int r = tid & 7;
        float zr = 0.f, zi = 0.f;
#pragma unroll
        for (int a = 0; a < 8; a++) {
            float  xv = sx[64 * a + b];
            float2 w  = stw[(64 * r * a) & NMASK];
            zr = fmaf(xv, w.x, zr);
            zi = fmaf(xv, w.y, zi);
        }
        sz[tid] = make_float2(zr, zi);
    }
    __syncthreads();

    // Stage C: thread k sums 64 terms
    {
        const int k = tid;
        const int r = k & 7;
        float ar = 0.f, ai = 0.f;
        int idx = 0;                   // (k*b) mod 512, incremental
#pragma unroll 8
        for (int b = 0; b < 64; b++) {
            float2 w = stw[idx];
            float2 z = sz[b * 8 + r];
            ar = fmaf(w.x, z.x, fmaf(-w.y, z.y, ar));
            ai = fmaf(w.x, z.y, fmaf( w.y, z.x, ai));
            idx = (idx + k) & NMASK;
        }
        g_y[(size_t)row * BN + k] = make_float2(ar, ai);
    }

    // Fused tail copy (target pass-through), if the output includes it
    {
        size_t o = (size_t)SRC_ELEMS + (size_t)row * BN + tid;
        if (o < (size_t)out_size) out[o] = sx[tid];
    }
}

// ---------------------------------------------------------------------------
// Bispectrum with Hermitian halving.
//   Bx[k,l] = y[k] * conj(y[l]) * y[(l-k)&511], mean over t.
//   Real input => Bx[l,k] = conj(Bx[k,l]).
// Tile i (k0 = 8i): compute k in [k0,k0+8), l in [k0,512).
//   direct: out[k][l]          (coalesced across warp lanes)
//   mirror: out[l][k0..k0+7]   for l >= k0+8  (32B-aligned float4 pairs)
// Coverage is exact and disjoint across tiles -> deterministic output.
// ---------------------------------------------------------------------------
__global__ void bispec_kernel(float* __restrict__ out) {
    __shared__ float2 sy[BT][BN];

    const int b  = blockIdx.y;
    const int k0 = blockIdx.x * KTILE;
    const int l  = threadIdx.x;

#pragma unroll
    for (int t = 0; t < BT; t++)
        sy[t][l] = g_y[((size_t)b * BT + t) * BN + l];
    __syncthreads();

    if (l < k0) return;                // no barriers after this point

    float lr[BT], li[BT];
#pragma unroll
    for (int t = 0; t < BT; t++) { lr[t] = sy[t][l].x; li[t] = sy[t][l].y; }

    float ar[KTILE], ai[KTILE];
#pragma unroll
    for (int kk = 0; kk < KTILE; kk++) {
        const int k = k0 + kk;
        const int m = (l - k) & NMASK;
        float Ar = 0.f, Ai = 0.f;
#pragma unroll
        for (int t = 0; t < BT; t++) {
            float2 yk = sy[t][k];      // broadcast, conflict-free
            float2 ym = sy[t][m];      // consecutive per lane
            // p = y[k] * conj(y[l])
            float pr = fmaf(yk.x, lr[t],  yk.y * li[t]);
            float pi = fmaf(yk.y, lr[t], -yk.x * li[t]);
            // Acc += p * y[m]
            Ar = fmaf(pr, ym.x, fmaf(-pi, ym.y, Ar));
            Ai = fmaf(pr, ym.y, fmaf( pi, ym.x, Ai));
        }
        ar[kk] = Ar * 0.25f;
        ai[kk] = Ai * 0.25f;
    }

    float* outb = out + (size_t)b * 2 * BN * BN;

    // Direct writes: rows k0..k0+7, column l (coalesced across the warp)
#pragma unroll
    for (int kk = 0; kk < KTILE; kk++) {
        outb[(size_t)(k0 + kk) * BN + l]                       = ar[kk];
        outb[(size_t)BN * BN + (size_t)(k0 + kk) * BN + l]     = ai[kk];
    }

    // Mirror writes: out[l][k0..k0+7] = conj(value); skip the diagonal block
    if (l >= k0 + KTILE) {
        float* pre = outb + (size_t)l * BN + k0;
        float* pim = outb + (size_t)BN * BN + (size_t)l * BN + k0;
        reinterpret_cast<float4*>(pre)[0] = make_float4( ar[0],  ar[1],  ar[2],  ar[3]);
        reinterpret_cast<float4*>(pre)[1] = make_float4( ar[4],  ar[5],  ar[6],  ar[7]);
        reinterpret_cast<float4*>(pim)[0] = make_float4(-ai[0], -ai[1], -ai[2], -ai[3]);
        reinterpret_cast<float4*>(pim)[1] = make_float4(-ai[4], -ai[5], -ai[6], -ai[7]);
    }
}

extern "C" void kernel_launch(void* const* d_in, const int* in_sizes, int n_in,
                              void* d_out, int out_size) {
    const float* x   = (const float*)d_in[0];
    float*       out = (float*)d_out;

    dft_kernel<<<BB * BT, BN>>>(x, out, out_size);
    bispec_kernel<<<dim3(BN / KTILE, BB), BN>>>(out);
}